// round 14
// baseline (speedup 1.0000x reference)
#include <cuda_runtime.h>
#include <cuda_bf16.h>

#define BATCH 4
#define CDIM  256
#define NDIM  4096
#define OC3   768

// Scratch (static device globals — no allocations allowed)
__device__ __nv_bfloat16 g_xb   [(size_t)BATCH * CDIM * NDIM];
__device__ __nv_bfloat16 g_wqkvb[(size_t)OC3 * CDIM];
__device__ __nv_bfloat16 g_wprjb[(size_t)CDIM * CDIM];
__device__ __nv_bfloat16 g_qkv  [(size_t)BATCH * OC3 * NDIM];   // [b][o][n] Q|K|V

// ---------------------------------------------------------------------------
__device__ __forceinline__ void cp16(void* smem_dst, const void* gsrc) {
    unsigned s = (unsigned)__cvta_generic_to_shared(smem_dst);
    asm volatile("cp.async.cg.shared.global [%0], [%1], 16;" :: "r"(s), "l"(gsrc));
}
__device__ __forceinline__ void cp_commit() {
    asm volatile("cp.async.commit_group;" ::: "memory");
}
__device__ __forceinline__ void cp_wait1() {
    asm volatile("cp.async.wait_group 1;" ::: "memory");
}
__device__ __forceinline__ void cp_wait0() {
    asm volatile("cp.async.wait_group 0;" ::: "memory");
}
__device__ __forceinline__ void ldsm4(unsigned r[4], const void* p) {
    unsigned a = (unsigned)__cvta_generic_to_shared(p);
    asm volatile("ldmatrix.sync.aligned.m8n8.x4.shared.b16 {%0,%1,%2,%3}, [%4];"
                 : "=r"(r[0]), "=r"(r[1]), "=r"(r[2]), "=r"(r[3]) : "r"(a));
}
__device__ __forceinline__ void ldsm4t(unsigned r[4], const void* p) {
    unsigned a = (unsigned)__cvta_generic_to_shared(p);
    asm volatile("ldmatrix.sync.aligned.m8n8.x4.trans.shared.b16 {%0,%1,%2,%3}, [%4];"
                 : "=r"(r[0]), "=r"(r[1]), "=r"(r[2]), "=r"(r[3]) : "r"(a));
}
__device__ __forceinline__ void mma16(float c[4], const unsigned a[4],
                                      const unsigned b0, const unsigned b1) {
    asm volatile(
        "mma.sync.aligned.m16n8k16.row.col.f32.bf16.bf16.f32 "
        "{%0,%1,%2,%3}, {%4,%5,%6,%7}, {%8,%9}, {%0,%1,%2,%3};"
        : "+f"(c[0]), "+f"(c[1]), "+f"(c[2]), "+f"(c[3])
        : "r"(a[0]), "r"(a[1]), "r"(a[2]), "r"(a[3]), "r"(b0), "r"(b1));
}
__device__ __forceinline__ unsigned packbf(float x, float y) {
    __nv_bfloat162 h = __float22bfloat162_rn(make_float2(x, y));
    return *(unsigned*)&h;
}

// ---------------------------------------------------------------------------
// Fused fp32 -> bf16 conversion for x, w_qkv, w_proj (one launch).
// ---------------------------------------------------------------------------
__global__ void f2b_all(const float* __restrict__ x,
                        const float* __restrict__ wq,
                        const float* __restrict__ wp) {
    const int N4X = (BATCH * CDIM * NDIM) / 4;
    const int N4Q = (OC3 * CDIM) / 4;
    const int N4P = (CDIM * CDIM) / 4;
    int i = blockIdx.x * blockDim.x + threadIdx.x;
    const float* s;
    __nv_bfloat16* d;
    int j;
    if (i < N4X)            { s = x;  d = g_xb;    j = i; }
    else if (i < N4X + N4Q) { s = wq; d = g_wqkvb; j = i - N4X; }
    else if (i < N4X + N4Q + N4P) { s = wp; d = g_wprjb; j = i - N4X - N4Q; }
    else return;
    float4 v = ((const float4*)s)[j];
    ((__nv_bfloat162*)d)[2 * j]     = __float22bfloat162_rn(make_float2(v.x, v.y));
    ((__nv_bfloat162*)d)[2 * j + 1] = __float22bfloat162_rn(make_float2(v.z, v.w));
}

// ---------------------------------------------------------------------------
// Generic bf16 GEMM (R5) — QKV only. (unchanged)
// ---------------------------------------------------------------------------
template<bool ATR, bool BTR, int EPI, bool OUTBF>
__global__ void __launch_bounds__(256, 2) gemm_bf16(
    const __nv_bfloat16* __restrict__ A, long lda, long aB,
    const __nv_bfloat16* __restrict__ B, long ldb, long bB,
    void* __restrict__ Cv, long cB,
    int KT, float scale,
    const float* __restrict__ bias,
    const float* __restrict__ X, long xB)
{
    constexpr int ASZ = ATR ? 32 * 136 : 128 * 40;
    constexpr int BSZ = BTR ? 32 * 136 : 128 * 40;
    __shared__ __align__(16) __nv_bfloat16 As[2][ASZ];
    __shared__ __align__(16) __nv_bfloat16 Bs[2][BSZ];

    const int bz = blockIdx.z;
    const int M0 = blockIdx.y * 128;
    const int N0 = blockIdx.x * 128;
    A += (size_t)bz * aB;
    B += (size_t)bz * bB;

    const int tid  = threadIdx.x;
    const int wid  = tid >> 5;
    const int lane = tid & 31;
    const int g    = lane >> 2;
    const int tg   = lane & 3;
    const int wm   = (wid & 3) * 32;
    const int wn   = (wid >> 2) * 64;

    int offA[2], offB[4];
    #pragma unroll
    for (int mt = 0; mt < 2; mt++) {
        const int m0 = wm + mt * 16;
        if (!ATR) offA[mt] = (m0 + (lane & 15)) * 80 + ((lane >> 4) << 4);
        else      offA[mt] = (((lane >> 4) << 3) + (lane & 7)) * 272
                           + m0 * 2 + (((lane >> 3) & 1) << 4);
    }
    #pragma unroll
    for (int nt2 = 0; nt2 < 4; nt2++) {
        const int n0 = wn + nt2 * 16;
        if (!BTR) offB[nt2] = (n0 + ((lane >> 4) << 3) + (lane & 7)) * 80
                            + (((lane >> 3) & 1) << 4);
        else      offB[nt2] = ((((lane >> 3) & 1) << 3) + (lane & 7)) * 272
                            + (n0 + ((lane >> 4) << 3)) * 2;
    }
    constexpr int stepA = ATR ? 16 * 272 : 32;
    constexpr int stepB = BTR ? 16 * 272 : 32;

    float acc[2][8][4];
    #pragma unroll
    for (int mt = 0; mt < 2; mt++)
        #pragma unroll
        for (int nt = 0; nt < 8; nt++)
            #pragma unroll
            for (int e = 0; e < 4; e++) acc[mt][nt][e] = 0.f;

    auto load_stage = [&](int c, int st) {
        const int kk0 = c * 32;
        if (!ATR) {
            #pragma unroll
            for (int e = tid; e < 512; e += 256) {
                int m = e >> 2, q = e & 3;
                cp16(&As[st][m * 40 + q * 8], A + (size_t)(M0 + m) * lda + kk0 + q * 8);
            }
        } else {
            #pragma unroll
            for (int e = tid; e < 512; e += 256) {
                int k = e >> 4, q = e & 15;
                cp16(&As[st][k * 136 + q * 8], A + (size_t)(kk0 + k) * lda + M0 + q * 8);
            }
        }
        if (!BTR) {
            #pragma unroll
            for (int e = tid; e < 512; e += 256) {
                int n = e >> 2, q = e & 3;
                cp16(&Bs[st][n * 40 + q * 8], B + (size_t)(N0 + n) * ldb + kk0 + q * 8);
            }
        } else {
            #pragma unroll
            for (int e = tid; e < 512; e += 256) {
                int k = e >> 4, q = e & 15;
                cp16(&Bs[st][k * 136 + q * 8], B + (size_t)(kk0 + k) * ldb + N0 + q * 8);
            }
        }
        cp_commit();
    };

    const int nc = KT / 32;
    load_stage(0, 0);
    for (int c = 0; c < nc; c++) {
        const int st = c & 1;
        if (c + 1 < nc) { load_stage(c + 1, st ^ 1); cp_wait1(); }
        else            { cp_wait0(); }
        __syncthreads();

        const char* Ab = (const char*)As[st];
        const char* Bb = (const char*)Bs[st];
        #pragma unroll
        for (int ks = 0; ks < 2; ks++) {
            unsigned a[2][4];
            #pragma unroll
            for (int mt = 0; mt < 2; mt++) {
                if (!ATR) ldsm4 (a[mt], Ab + offA[mt] + ks * stepA);
                else      ldsm4t(a[mt], Ab + offA[mt] + ks * stepA);
            }
            #pragma unroll
            for (int nt2 = 0; nt2 < 4; nt2++) {
                unsigned b[4];
                if (!BTR) ldsm4 (b, Bb + offB[nt2] + ks * stepB);
                else      ldsm4t(b, Bb + offB[nt2] + ks * stepB);
                #pragma unroll
                for (int mt = 0; mt < 2; mt++) {
                    mma16(acc[mt][2 * nt2],     a[mt], b[0], b[1]);
                    mma16(acc[mt][2 * nt2 + 1], a[mt], b[2], b[3]);
                }
            }
        }
        __syncthreads();
    }

    float* Cf = (float*)Cv + (size_t)bz * cB;
    __nv_bfloat16* Cb = (__nv_bfloat16*)Cv + (size_t)bz * cB;
    if (EPI == 3) X += (size_t)bz * xB;

    #pragma unroll
    for (int mt = 0; mt < 2; mt++) {
        const int r0 = M0 + wm + mt * 16 + g;
        const int r1 = r0 + 8;
        float bv0 = 0.f, bv1 = 0.f;
        if (EPI >= 2) { bv0 = bias[r0]; bv1 = bias[r1]; }
        #pragma unroll
        for (int nt = 0; nt < 8; nt++) {
            const int col = N0 + wn + nt * 8 + 2 * tg;
            float v00 = acc[mt][nt][0], v01 = acc[mt][nt][1];
            float v10 = acc[mt][nt][2], v11 = acc[mt][nt][3];
            if (EPI == 1) { v00 *= scale; v01 *= scale; v10 *= scale; v11 *= scale; }
            if (EPI >= 2) { v00 += bv0; v01 += bv0; v10 += bv1; v11 += bv1; }
            if (EPI == 3) {
                const float2 x0 = *(const float2*)(X + (size_t)r0 * NDIM + col);
                const float2 x1 = *(const float2*)(X + (size_t)r1 * NDIM + col);
                v00 += x0.x; v01 += x0.y; v10 += x1.x; v11 += x1.y;
            }
            if (OUTBF) {
                *(__nv_bfloat162*)(Cb + (size_t)r0 * NDIM + col) =
                    __float22bfloat162_rn(make_float2(v00, v01));
                *(__nv_bfloat162*)(Cb + (size_t)r1 * NDIM + col) =
                    __float22bfloat162_rn(make_float2(v10, v11));
            } else {
                *(float2*)(Cf + (size_t)r0 * NDIM + col) = make_float2(v00, v01);
                *(float2*)(Cf + (size_t)r1 * NDIM + col) = make_float2(v10, v11);
            }
        }
    }
}

// ---------------------------------------------------------------------------
// Fused flash attention + projection + residual — 2 CTAs/SM, swizzled tiles.
// CTA = 64 queries, 128 threads (4 warps x 16 queries), 32-key chunks.
// smem (bytes): Q 256x144 (pad) | K[2] 256x64 swz | V[2] 256x64 swz = 102400
// Wp half (128o x 512B, swz) exactly overlays K/V region (65536 B).
// All cp.async dsts and ldmatrix row addrs are 16B-aligned (audited).
// K/V swizzle: quad q at position q ^ ((row>>1)&3). Wp: q ^ (row&7).
// ---------------------------------------------------------------------------
#define QS2_ELEM  (256 * 72)     // 36864 B
#define KV2_ELEM  (256 * 32)     // 16384 B per buffer
#define FLASH_SMEM ((QS2_ELEM + 4 * KV2_ELEM) * 2)   // 102400 bytes

__global__ void __launch_bounds__(128, 2) flash_attn(
    const float* __restrict__ x,
    const float* __restrict__ bias,
    float* __restrict__ out)
{
    extern __shared__ __align__(16) __nv_bfloat16 sm[];
    __nv_bfloat16* Qs = sm;
    __nv_bfloat16* Ks = sm + QS2_ELEM;
    __nv_bfloat16* Vs = sm + QS2_ELEM + 2 * KV2_ELEM;
    __nv_bfloat16* Ws = sm + QS2_ELEM;             // Wp half overlays K/V region

    const int b  = blockIdx.y;
    const int M0 = blockIdx.x * 64;
    const __nv_bfloat16* Qg = g_qkv + (size_t)b * OC3 * NDIM;
    const __nv_bfloat16* Kg = Qg + (size_t)CDIM * NDIM;
    const __nv_bfloat16* Vg = Kg + (size_t)CDIM * NDIM;

    const int tid  = threadIdx.x;
    const int w    = tid >> 5;      // 0..3
    const int lane = tid & 31;
    const int g    = lane >> 2;
    const int tg   = lane & 3;
    const int hb   = (lane >> 3) & 1;

    // Q fragment offsets: rows = channel (144B stride), cols = query
    const int offQ = (((lane >> 4) << 3) + (lane & 7)) * 144
                   + (w * 16) * 2 + (hb << 4);
    // K: rows = channel within 16-chunk (64B swizzled rows), quad = j-block
    const int rkK = (hb << 3) + (lane & 7);           // 0..15
    int offK[2];
    #pragma unroll
    for (int nt2 = 0; nt2 < 2; nt2++) {
        const int qj = nt2 * 2 + (lane >> 4);         // 0..3
        offK[nt2] = rkK * 64 + ((qj ^ ((rkK >> 1) & 3)) << 4);
    }
    // V: rows = channel within 16-chunk, quad = j-block (t*2 + hb)
    const int rvV = ((lane >> 4) << 3) + (lane & 7);  // 0..15
    int offV[2];
    #pragma unroll
    for (int t = 0; t < 2; t++) {
        const int qv = t * 2 + hb;
        offV[t] = rvV * 64 + ((qv ^ ((rvV >> 1) & 3)) << 4);
    }
    // Wp: rows = o within 16-chunk (512B swizzled rows), quad varies with kc
    const int roW = ((lane >> 4) << 3) + (lane & 7);  // 0..15
    const int xorW = roW & 7;

    float acc[32][4];
    #pragma unroll
    for (int nt = 0; nt < 32; nt++)
        #pragma unroll
        for (int e = 0; e < 4; e++) acc[nt][e] = 0.f;
    float l0 = 0.f, l1 = 0.f;

    // Q tile: 256c x 64q = 2048 x 16B (row stride 72 elems = 144 B)
    #pragma unroll
    for (int e = tid; e < 2048; e += 128) {
        int r = e >> 3, q = e & 7;
        cp16(&Qs[r * 72 + q * 8], Qg + (size_t)r * NDIM + M0 + q * 8);
    }
    auto load_kv = [&](int jc, int st) {
        const int j0 = jc * 32;
        #pragma unroll
        for (int e = tid; e < 1024; e += 128) {
            int r = e >> 2, q = e & 3;
            int sq = q ^ ((r >> 1) & 3);
            cp16(&Ks[st * KV2_ELEM + r * 32 + sq * 8], Kg + (size_t)r * NDIM + j0 + q * 8);
        }
        #pragma unroll
        for (int e = tid; e < 1024; e += 128) {
            int r = e >> 2, q = e & 3;
            int sq = q ^ ((r >> 1) & 3);
            cp16(&Vs[st * KV2_ELEM + r * 32 + sq * 8], Vg + (size_t)r * NDIM + j0 + q * 8);
        }
        cp_commit();
    };

    load_kv(0, 0);
    const float SC = 0.0625f;  // 1/sqrt(256)

    for (int jc = 0; jc < NDIM / 32; jc++) {
        const int st = jc & 1;
        if (jc + 1 < NDIM / 32) { load_kv(jc + 1, st ^ 1); cp_wait1(); }
        else                    { cp_wait0(); }
        __syncthreads();

        // ---- S = Q^T K  (16q x 32k x 256c per warp) ----
        float sacc[4][4];
        #pragma unroll
        for (int nt = 0; nt < 4; nt++)
            #pragma unroll
            for (int e = 0; e < 4; e++) sacc[nt][e] = 0.f;

        const char* Qb = (const char*)Qs;
        const char* Kb = (const char*)(Ks + st * KV2_ELEM);
        #pragma unroll
        for (int kc = 0; kc < 16; kc++) {
            unsigned aq[4];
            ldsm4t(aq, Qb + offQ + kc * 2304);     // 16 rows x 144 B
            #pragma unroll
            for (int nt2 = 0; nt2 < 2; nt2++) {
                unsigned bk[4];
                ldsm4t(bk, Kb + offK[nt2] + kc * 1024);  // 16 rows x 64 B
                mma16(sacc[2 * nt2],     aq, bk[0], bk[1]);
                mma16(sacc[2 * nt2 + 1], aq, bk[2], bk[3]);
            }
        }

        // ---- no-max softmax: P = exp(S/16) ----
        unsigned pe[4][2];
        float ps0 = 0.f, ps1 = 0.f;
        #pragma unroll
        for (int nt = 0; nt < 4; nt++) {
            float e0 = __expf(sacc[nt][0] * SC);
            float e1 = __expf(sacc[nt][1] * SC);
            float e2 = __expf(sacc[nt][2] * SC);
            float e3 = __expf(sacc[nt][3] * SC);
            pe[nt][0] = packbf(e0, e1);
            pe[nt][1] = packbf(e2, e3);
            ps0 += e0 + e1;
            ps1 += e2 + e3;
        }
        l0 += ps0;
        l1 += ps1;

        // ---- O += P V^T  (16q x 256c x 32k) ----
        const char* Vb = (const char*)(Vs + st * KV2_ELEM);
        #pragma unroll
        for (int t = 0; t < 2; t++) {
            unsigned a[4] = { pe[2 * t][0], pe[2 * t][1], pe[2 * t + 1][0], pe[2 * t + 1][1] };
            #pragma unroll
            for (int ct = 0; ct < 16; ct++) {
                unsigned bv[4];
                ldsm4(bv, Vb + offV[t] + ct * 1024);
                mma16(acc[2 * ct],     a, bv[0], bv[1]);
                mma16(acc[2 * ct + 1], a, bv[2], bv[3]);
            }
        }
        __syncthreads();
    }

    // ---- normalize O, pack to bf16 A-fragments ----
    l0 += __shfl_xor_sync(0xffffffffu, l0, 1);
    l0 += __shfl_xor_sync(0xffffffffu, l0, 2);
    l1 += __shfl_xor_sync(0xffffffffu, l1, 1);
    l1 += __shfl_xor_sync(0xffffffffu, l1, 2);
    const float inv0 = 1.f / l0, inv1 = 1.f / l1;

    unsigned pk[64];
    #pragma unroll
    for (int kc = 0; kc < 16; kc++) {
        pk[4 * kc + 0] = packbf(acc[2 * kc][0] * inv0,     acc[2 * kc][1] * inv0);
        pk[4 * kc + 1] = packbf(acc[2 * kc][2] * inv1,     acc[2 * kc][3] * inv1);
        pk[4 * kc + 2] = packbf(acc[2 * kc + 1][0] * inv0, acc[2 * kc + 1][1] * inv0);
        pk[4 * kc + 3] = packbf(acc[2 * kc + 1][2] * inv1, acc[2 * kc + 1][3] * inv1);
    }

    // ---- proj in 2 halves of 128 o-channels each ----
    const float* Xb = x + (size_t)b * CDIM * NDIM;
    float* Ob = out + (size_t)b * CDIM * NDIM;
    float* sE = (float*)sm;                    // [64][68] fp32, overlays Q region
    const char* Wb = (const char*)Ws;
    const int colw = 16 * w + g;

    #pragma unroll
    for (int half = 0; half < 2; half++) {
        __syncthreads();   // prior readers of Ws / sE regions done
        // Wp half: 128 o-rows x 512B swizzled rows
        #pragma unroll
        for (int e = tid; e < 4096; e += 128) {
            int r = e >> 5, q = e & 31;
            int sq = q ^ (r & 7);
            cp16(&Ws[r * 256 + sq * 8],
                 g_wprjb + (size_t)(half * 128 + r) * CDIM + q * 8);
        }
        cp_commit();
        cp_wait0();
        __syncthreads();

        float racc[16][4];
        #pragma unroll
        for (int ot = 0; ot < 16; ot++)
            #pragma unroll
            for (int e = 0; e < 4; e++) racc[ot][e] = 0.f;

        #pragma unroll
        for (int kc = 0; kc < 16; kc++) {
            unsigned a[4] = { pk[4 * kc], pk[4 * kc + 1], pk[4 * kc + 2], pk[4 * kc + 3] };
            const int qbase = kc * 2 + hb;
            const int swoff = roW * 512 + ((qbase ^ xorW) << 4);
            #pragma unroll
            for (int ot2 = 0; ot2 < 8; ot2++) {
                unsigned bw[4];
                ldsm4(bw, Wb + swoff + ot2 * 8192);   // 16 o-rows x 512 B
                mma16(racc[2 * ot2],     a, bw[0], bw[1]);
                mma16(racc[2 * ot2 + 1], a, bw[2], bw[3]);
            }
        }

        // stage + store 2 blocks of 64 o-rows
        #pragma unroll
        for (int hh = 0; hh < 2; hh++) {
            __syncthreads();
            #pragma unroll
            for (int k = 0; k < 8; k++) {
                const int ot = hh * 8 + k;
                const int ol = 8 * k + 2 * tg;
                sE[ol * 68 + colw]           = racc[ot][0];
                sE[(ol + 1) * 68 + colw]     = racc[ot][1];
                sE[ol * 68 + colw + 8]       = racc[ot][2];
                sE[(ol + 1) * 68 + colw + 8] = racc[ot][3];
            }
            __syncthreads();
            #pragma unroll
            for (int it = 0; it < 8; it++) {
                const int e = tid + it * 128;
                const int ol = e >> 4, ic = (e & 15) * 4;
                const int o = half * 128 + hh * 64 + ol;
                const float4 xv = *(const float4*)(Xb + (size_t)o * NDIM + M0 + ic);
                const float bv = bias[o];
                float4 r;
                r.x = sE[ol * 68 + ic]     + xv.x + bv;
                r.y = sE[ol * 68 + ic + 1] + xv.y + bv;
                r.z = sE[ol * 68 + ic + 2] + xv.z + bv;
                r.w = sE[ol * 68 + ic + 3] + xv.w + bv;
                *(float4*)(Ob + (size_t)o * NDIM + M0 + ic) = r;
            }
        }
    }
}

// ---------------------------------------------------------------------------
extern "C" void kernel_launch(void* const* d_in, const int* in_sizes, int n_in,
                              void* d_out, int out_size) {
    const float* x      = (const float*)d_in[0];
    const float* w_qkv  = (const float*)d_in[1];
    const float* b_qkv  = (const float*)d_in[2];
    const float* w_proj = (const float*)d_in[3];
    const float* b_proj = (const float*)d_in[4];
    float* out = (float*)d_out;

    __nv_bfloat16 *xb, *wqb, *qkv;
    cudaGetSymbolAddress((void**)&xb,  g_xb);
    cudaGetSymbolAddress((void**)&wqb, g_wqkvb);
    cudaGetSymbolAddress((void**)&qkv, g_qkv);

    cudaFuncSetAttribute(flash_attn,
                         cudaFuncAttributeMaxDynamicSharedMemorySize, FLASH_SMEM);

    // fused fp32->bf16 conversions (one launch)
    {
        const int n4 = (BATCH * CDIM * NDIM + OC3 * CDIM + CDIM * CDIM) / 4;
        f2b_all<<<(n4 + 255) / 256, 256>>>(x, w_qkv, w_proj);
    }

    // 1) QKV: C[o][n] = W[o][c] X[c][n] + b
    gemm_bf16<false, true, 2, true><<<dim3(NDIM / 128, OC3 / 128, BATCH), 256>>>(
        wqb, CDIM, 0,
        xb, NDIM, (long)CDIM * NDIM,
        qkv, (long)OC3 * NDIM,
        CDIM, 1.f, b_qkv, nullptr, 0);

    // 2) fused attention + projection + residual -> out  (64q CTAs, 2/SM)
    flash_attn<<<dim3(NDIM / 64, BATCH), 128, FLASH_SMEM>>>(x, b_proj, out);
}

// round 16
// speedup vs baseline: 1.0386x; 1.0386x over previous
#include <cuda_runtime.h>
#include <cuda_bf16.h>

#define BATCH 4
#define CDIM  256
#define NDIM  4096
#define OC3   768

// Scratch (static device globals — no allocations allowed)
__device__ __nv_bfloat16 g_xb   [(size_t)BATCH * CDIM * NDIM];
__device__ __nv_bfloat16 g_wqkvb[(size_t)OC3 * CDIM];
__device__ __nv_bfloat16 g_wprjb[(size_t)CDIM * CDIM];
__device__ __nv_bfloat16 g_qkv  [(size_t)BATCH * OC3 * NDIM];   // [b][o][n] Q|K|V

// ---------------------------------------------------------------------------
__device__ __forceinline__ void cp16(void* smem_dst, const void* gsrc) {
    unsigned s = (unsigned)__cvta_generic_to_shared(smem_dst);
    asm volatile("cp.async.cg.shared.global [%0], [%1], 16;" :: "r"(s), "l"(gsrc));
}
__device__ __forceinline__ void cp_commit() {
    asm volatile("cp.async.commit_group;" ::: "memory");
}
__device__ __forceinline__ void cp_wait0() {
    asm volatile("cp.async.wait_group 0;" ::: "memory");
}
__device__ __forceinline__ void ldsm4(unsigned r[4], const void* p) {
    unsigned a = (unsigned)__cvta_generic_to_shared(p);
    asm volatile("ldmatrix.sync.aligned.m8n8.x4.shared.b16 {%0,%1,%2,%3}, [%4];"
                 : "=r"(r[0]), "=r"(r[1]), "=r"(r[2]), "=r"(r[3]) : "r"(a));
}
__device__ __forceinline__ void ldsm4t(unsigned r[4], const void* p) {
    unsigned a = (unsigned)__cvta_generic_to_shared(p);
    asm volatile("ldmatrix.sync.aligned.m8n8.x4.trans.shared.b16 {%0,%1,%2,%3}, [%4];"
                 : "=r"(r[0]), "=r"(r[1]), "=r"(r[2]), "=r"(r[3]) : "r"(a));
}
__device__ __forceinline__ void mma16(float c[4], const unsigned a[4],
                                      const unsigned b0, const unsigned b1) {
    asm volatile(
        "mma.sync.aligned.m16n8k16.row.col.f32.bf16.bf16.f32 "
        "{%0,%1,%2,%3}, {%4,%5,%6,%7}, {%8,%9}, {%0,%1,%2,%3};"
        : "+f"(c[0]), "+f"(c[1]), "+f"(c[2]), "+f"(c[3])
        : "r"(a[0]), "r"(a[1]), "r"(a[2]), "r"(a[3]), "r"(b0), "r"(b1));
}
__device__ __forceinline__ unsigned packbf(float x, float y) {
    __nv_bfloat162 h = __float22bfloat162_rn(make_float2(x, y));
    return *(unsigned*)&h;
}

// ---------------------------------------------------------------------------
// Fused fp32 -> bf16 conversion for x, w_qkv, w_proj (one launch).
// ---------------------------------------------------------------------------
__global__ void f2b_all(const float* __restrict__ x,
                        const float* __restrict__ wq,
                        const float* __restrict__ wp) {
    const int N4X = (BATCH * CDIM * NDIM) / 4;
    const int N4Q = (OC3 * CDIM) / 4;
    const int N4P = (CDIM * CDIM) / 4;
    int i = blockIdx.x * blockDim.x + threadIdx.x;
    const float* s;
    __nv_bfloat16* d;
    int j;
    if (i < N4X)            { s = x;  d = g_xb;    j = i; }
    else if (i < N4X + N4Q) { s = wq; d = g_wqkvb; j = i - N4X; }
    else if (i < N4X + N4Q + N4P) { s = wp; d = g_wprjb; j = i - N4X - N4Q; }
    else return;
    float4 v = ((const float4*)s)[j];
    ((__nv_bfloat162*)d)[2 * j]     = __float22bfloat162_rn(make_float2(v.x, v.y));
    ((__nv_bfloat162*)d)[2 * j + 1] = __float22bfloat162_rn(make_float2(v.z, v.w));
}

// ---------------------------------------------------------------------------
// Generic bf16 GEMM — QKV only. Single sync per K-chunk (load after sync).
// ---------------------------------------------------------------------------
template<bool ATR, bool BTR, int EPI, bool OUTBF>
__global__ void __launch_bounds__(256, 2) gemm_bf16(
    const __nv_bfloat16* __restrict__ A, long lda, long aB,
    const __nv_bfloat16* __restrict__ B, long ldb, long bB,
    void* __restrict__ Cv, long cB,
    int KT, float scale,
    const float* __restrict__ bias,
    const float* __restrict__ X, long xB)
{
    constexpr int ASZ = ATR ? 32 * 136 : 128 * 40;
    constexpr int BSZ = BTR ? 32 * 136 : 128 * 40;
    __shared__ __align__(16) __nv_bfloat16 As[2][ASZ];
    __shared__ __align__(16) __nv_bfloat16 Bs[2][BSZ];

    const int bz = blockIdx.z;
    const int M0 = blockIdx.y * 128;
    const int N0 = blockIdx.x * 128;
    A += (size_t)bz * aB;
    B += (size_t)bz * bB;

    const int tid  = threadIdx.x;
    const int wid  = tid >> 5;
    const int lane = tid & 31;
    const int g    = lane >> 2;
    const int tg   = lane & 3;
    const int wm   = (wid & 3) * 32;
    const int wn   = (wid >> 2) * 64;

    int offA[2], offB[4];
    #pragma unroll
    for (int mt = 0; mt < 2; mt++) {
        const int m0 = wm + mt * 16;
        if (!ATR) offA[mt] = (m0 + (lane & 15)) * 80 + ((lane >> 4) << 4);
        else      offA[mt] = (((lane >> 4) << 3) + (lane & 7)) * 272
                           + m0 * 2 + (((lane >> 3) & 1) << 4);
    }
    #pragma unroll
    for (int nt2 = 0; nt2 < 4; nt2++) {
        const int n0 = wn + nt2 * 16;
        if (!BTR) offB[nt2] = (n0 + ((lane >> 4) << 3) + (lane & 7)) * 80
                            + (((lane >> 3) & 1) << 4);
        else      offB[nt2] = ((((lane >> 3) & 1) << 3) + (lane & 7)) * 272
                            + (n0 + ((lane >> 4) << 3)) * 2;
    }
    constexpr int stepA = ATR ? 16 * 272 : 32;
    constexpr int stepB = BTR ? 16 * 272 : 32;

    float acc[2][8][4];
    #pragma unroll
    for (int mt = 0; mt < 2; mt++)
        #pragma unroll
        for (int nt = 0; nt < 8; nt++)
            #pragma unroll
            for (int e = 0; e < 4; e++) acc[mt][nt][e] = 0.f;

    auto load_stage = [&](int c, int st) {
        const int kk0 = c * 32;
        if (!ATR) {
            #pragma unroll
            for (int e = tid; e < 512; e += 256) {
                int m = e >> 2, q = e & 3;
                cp16(&As[st][m * 40 + q * 8], A + (size_t)(M0 + m) * lda + kk0 + q * 8);
            }
        } else {
            #pragma unroll
            for (int e = tid; e < 512; e += 256) {
                int k = e >> 4, q = e & 15;
                cp16(&As[st][k * 136 + q * 8], A + (size_t)(kk0 + k) * lda + M0 + q * 8);
            }
        }
        if (!BTR) {
            #pragma unroll
            for (int e = tid; e < 512; e += 256) {
                int n = e >> 2, q = e & 3;
                cp16(&Bs[st][n * 40 + q * 8], B + (size_t)(N0 + n) * ldb + kk0 + q * 8);
            }
        } else {
            #pragma unroll
            for (int e = tid; e < 512; e += 256) {
                int k = e >> 4, q = e & 15;
                cp16(&Bs[st][k * 136 + q * 8], B + (size_t)(kk0 + k) * ldb + N0 + q * 8);
            }
        }
        cp_commit();
    };

    const int nc = KT / 32;
    load_stage(0, 0);
    for (int c = 0; c < nc; c++) {
        const int st = c & 1;
        cp_wait0();          // chunk c complete (only outstanding group)
        __syncthreads();     // visibility + prior-buffer reads done
        if (c + 1 < nc) load_stage(c + 1, st ^ 1);   // overlaps compute below

        const char* Ab = (const char*)As[st];
        const char* Bb = (const char*)Bs[st];
        #pragma unroll
        for (int ks = 0; ks < 2; ks++) {
            unsigned a[2][4];
            #pragma unroll
            for (int mt = 0; mt < 2; mt++) {
                if (!ATR) ldsm4 (a[mt], Ab + offA[mt] + ks * stepA);
                else      ldsm4t(a[mt], Ab + offA[mt] + ks * stepA);
            }
            #pragma unroll
            for (int nt2 = 0; nt2 < 4; nt2++) {
                unsigned b[4];
                if (!BTR) ldsm4 (b, Bb + offB[nt2] + ks * stepB);
                else      ldsm4t(b, Bb + offB[nt2] + ks * stepB);
                #pragma unroll
                for (int mt = 0; mt < 2; mt++) {
                    mma16(acc[mt][2 * nt2],     a[mt], b[0], b[1]);
                    mma16(acc[mt][2 * nt2 + 1], a[mt], b[2], b[3]);
                }
            }
        }
    }

    float* Cf = (float*)Cv + (size_t)bz * cB;
    __nv_bfloat16* Cb = (__nv_bfloat16*)Cv + (size_t)bz * cB;
    if (EPI == 3) X += (size_t)bz * xB;

    #pragma unroll
    for (int mt = 0; mt < 2; mt++) {
        const int r0 = M0 + wm + mt * 16 + g;
        const int r1 = r0 + 8;
        float bv0 = 0.f, bv1 = 0.f;
        if (EPI >= 2) { bv0 = bias[r0]; bv1 = bias[r1]; }
        #pragma unroll
        for (int nt = 0; nt < 8; nt++) {
            const int col = N0 + wn + nt * 8 + 2 * tg;
            float v00 = acc[mt][nt][0], v01 = acc[mt][nt][1];
            float v10 = acc[mt][nt][2], v11 = acc[mt][nt][3];
            if (EPI == 1) { v00 *= scale; v01 *= scale; v10 *= scale; v11 *= scale; }
            if (EPI >= 2) { v00 += bv0; v01 += bv0; v10 += bv1; v11 += bv1; }
            if (EPI == 3) {
                const float2 x0 = *(const float2*)(X + (size_t)r0 * NDIM + col);
                const float2 x1 = *(const float2*)(X + (size_t)r1 * NDIM + col);
                v00 += x0.x; v01 += x0.y; v10 += x1.x; v11 += x1.y;
            }
            if (OUTBF) {
                *(__nv_bfloat162*)(Cb + (size_t)r0 * NDIM + col) =
                    __float22bfloat162_rn(make_float2(v00, v01));
                *(__nv_bfloat162*)(Cb + (size_t)r1 * NDIM + col) =
                    __float22bfloat162_rn(make_float2(v10, v11));
            } else {
                *(float2*)(Cf + (size_t)r0 * NDIM + col) = make_float2(v00, v01);
                *(float2*)(Cf + (size_t)r1 * NDIM + col) = make_float2(v10, v11);
            }
        }
    }
}

// ---------------------------------------------------------------------------
// Fused flash attention + projection + residual (R12 structure).
// Block = 128 queries of one batch. 8 warps x 16 queries.
// SINGLE __syncthreads per 64-key chunk (load issued after the sync).
// smem: Q [256c][136] | K[2][256c][72] | V[2][256c][72]; Wp overlays K/V;
//       epilogue staging [64][132] fp32 overlays Q region.
// ---------------------------------------------------------------------------
#define QS_ELEM  (256 * 136)
#define KV_ELEM  (256 * 72)
#define FLASH_SMEM ((QS_ELEM + 4 * KV_ELEM) * 2)   // bytes = 217088

__global__ void __launch_bounds__(256, 1) flash_attn(
    const float* __restrict__ x,      // fp32 input (residual)
    const float* __restrict__ bias,   // proj bias
    float* __restrict__ out)
{
    extern __shared__ __align__(16) __nv_bfloat16 sm[];
    __nv_bfloat16* Qs = sm;
    __nv_bfloat16* Ks = sm + QS_ELEM;
    __nv_bfloat16* Vs = sm + QS_ELEM + 2 * KV_ELEM;
    __nv_bfloat16* Ws = sm + QS_ELEM;              // Wp overlays K/V region

    const int b  = blockIdx.y;
    const int M0 = blockIdx.x * 128;
    const __nv_bfloat16* Qg = g_qkv + (size_t)b * OC3 * NDIM;
    const __nv_bfloat16* Kg = Qg + (size_t)CDIM * NDIM;
    const __nv_bfloat16* Vg = Kg + (size_t)CDIM * NDIM;

    const int tid  = threadIdx.x;
    const int w    = tid >> 5;
    const int lane = tid & 31;
    const int g    = lane >> 2;
    const int tg   = lane & 3;

    const int offQ = (((lane >> 4) << 3) + (lane & 7)) * 272
                   + (w * 16) * 2 + (((lane >> 3) & 1) << 4);
    int offK[4];
    #pragma unroll
    for (int nt2 = 0; nt2 < 4; nt2++)
        offK[nt2] = ((((lane >> 3) & 1) << 3) + (lane & 7)) * 144
                  + (nt2 * 16 + ((lane >> 4) << 3)) * 2;
    const int offV = (((lane >> 4) << 3) + (lane & 7)) * 144 + (((lane >> 3) & 1) << 4);
    const int offW0 = (((lane >> 4) << 3) + (lane & 7)) * 528 + (((lane >> 3) & 1) << 4);

    float acc[32][4];
    #pragma unroll
    for (int nt = 0; nt < 32; nt++)
        #pragma unroll
        for (int e = 0; e < 4; e++) acc[nt][e] = 0.f;
    float l0 = 0.f, l1 = 0.f;

    // load Q (256c x 128q tile: 4096 x 16B)
    #pragma unroll
    for (int e = tid; e < 4096; e += 256) {
        int r = e >> 4, q = e & 15;
        cp16(&Qs[r * 136 + q * 8], Qg + (size_t)r * NDIM + M0 + q * 8);
    }
    auto load_kv = [&](int jc, int st) {
        const int j0 = jc * 64;
        #pragma unroll
        for (int e = tid; e < 2048; e += 256) {
            int r = e >> 3, q = e & 7;
            cp16(&Ks[st * KV_ELEM + r * 72 + q * 8], Kg + (size_t)r * NDIM + j0 + q * 8);
        }
        #pragma unroll
        for (int e = tid; e < 2048; e += 256) {
            int r = e >> 3, q = e & 7;
            cp16(&Vs[st * KV_ELEM + r * 72 + q * 8], Vg + (size_t)r * NDIM + j0 + q * 8);
        }
        cp_commit();
    };

    load_kv(0, 0);
    const float SC = 0.0625f;  // 1/sqrt(256)

    for (int jc = 0; jc < NDIM / 64; jc++) {
        const int st = jc & 1;
        cp_wait0();          // chunk jc complete (only outstanding group)
        __syncthreads();     // visibility; all warps done reading buffer st^1
        if (jc + 1 < NDIM / 64) load_kv(jc + 1, st ^ 1);  // overlaps compute

        // ---- S = Q^T K ----
        float sacc[8][4];
        #pragma unroll
        for (int nt = 0; nt < 8; nt++)
            #pragma unroll
            for (int e = 0; e < 4; e++) sacc[nt][e] = 0.f;

        const char* Qb = (const char*)Qs;
        const char* Kb = (const char*)(Ks + st * KV_ELEM);
        #pragma unroll
        for (int kc = 0; kc < 16; kc++) {
            unsigned aq[4];
            ldsm4t(aq, Qb + offQ + kc * 4352);
            #pragma unroll
            for (int nt2 = 0; nt2 < 4; nt2++) {
                unsigned bk[4];
                ldsm4t(bk, Kb + offK[nt2] + kc * 2304);
                mma16(sacc[2 * nt2],     aq, bk[0], bk[1]);
                mma16(sacc[2 * nt2 + 1], aq, bk[2], bk[3]);
            }
        }

        // ---- no-max softmax: P = exp(S/16), accumulate row sums ----
        unsigned pe[8][2];
        float ps0 = 0.f, ps1 = 0.f;
        #pragma unroll
        for (int nt = 0; nt < 8; nt++) {
            float e0 = __expf(sacc[nt][0] * SC);
            float e1 = __expf(sacc[nt][1] * SC);
            float e2 = __expf(sacc[nt][2] * SC);
            float e3 = __expf(sacc[nt][3] * SC);
            pe[nt][0] = packbf(e0, e1);
            pe[nt][1] = packbf(e2, e3);
            ps0 += e0 + e1;
            ps1 += e2 + e3;
        }
        l0 += ps0;
        l1 += ps1;

        // ---- O += P V^T ----
        const char* Vb = (const char*)(Vs + st * KV_ELEM);
        #pragma unroll
        for (int t = 0; t < 4; t++) {
            unsigned a[4] = { pe[2 * t][0], pe[2 * t][1], pe[2 * t + 1][0], pe[2 * t + 1][1] };
            #pragma unroll
            for (int ct = 0; ct < 16; ct++) {
                unsigned bv[4];
                ldsm4(bv, Vb + offV + ct * 2304 + t * 32);
                mma16(acc[2 * ct],     a, bv[0], bv[1]);
                mma16(acc[2 * ct + 1], a, bv[2], bv[3]);
            }
        }
    }
    __syncthreads();   // last chunk's V reads done before Wp overlays K/V

    // ---- load Wp into freed K/V smem: [o=256][c=256] bf16, 528B rows ----
    #pragma unroll
    for (int e = tid; e < 8192; e += 256) {
        int r = e >> 5, q = e & 31;
        cp16(&Ws[r * 264 + q * 8], g_wprjb + (size_t)r * CDIM + q * 8);
    }
    cp_commit();
    cp_wait0();

    // ---- normalize O and pack to bf16 A-fragments ----
    l0 += __shfl_xor_sync(0xffffffffu, l0, 1);
    l0 += __shfl_xor_sync(0xffffffffu, l0, 2);
    l1 += __shfl_xor_sync(0xffffffffu, l1, 1);
    l1 += __shfl_xor_sync(0xffffffffu, l1, 2);
    const float inv0 = 1.f / l0, inv1 = 1.f / l1;

    unsigned pk[64];
    #pragma unroll
    for (int kc = 0; kc < 16; kc++) {
        pk[4 * kc + 0] = packbf(acc[2 * kc][0] * inv0,     acc[2 * kc][1] * inv0);
        pk[4 * kc + 1] = packbf(acc[2 * kc][2] * inv1,     acc[2 * kc][3] * inv1);
        pk[4 * kc + 2] = packbf(acc[2 * kc + 1][0] * inv0, acc[2 * kc + 1][1] * inv0);
        pk[4 * kc + 3] = packbf(acc[2 * kc + 1][2] * inv1, acc[2 * kc + 1][3] * inv1);
    }
    __syncthreads();   // Wp visible to all warps

    // ---- proj: R[i][o] = O_norm[i][c] * Wp[o][c]  (m16 x n256 x k256) ----
    float racc[32][4];
    #pragma unroll
    for (int ot = 0; ot < 32; ot++)
        #pragma unroll
        for (int e = 0; e < 4; e++) racc[ot][e] = 0.f;

    const char* Wb = (const char*)Ws;
    #pragma unroll
    for (int kc = 0; kc < 16; kc++) {
        unsigned a[4] = { pk[4 * kc], pk[4 * kc + 1], pk[4 * kc + 2], pk[4 * kc + 3] };
        #pragma unroll
        for (int ot2 = 0; ot2 < 16; ot2++) {
            unsigned bw[4];
            ldsm4(bw, Wb + offW0 + ot2 * 8448 + kc * 32);
            mma16(racc[2 * ot2],     a, bw[0], bw[1]);
            mma16(racc[2 * ot2 + 1], a, bw[2], bw[3]);
        }
    }

    // ---- stage R through smem (overlay Q region) for coalesced stores ----
    float* sE = (float*)sm;                    // [64][132] fp32 = 33.8 KB
    const float* Xb = x + (size_t)b * CDIM * NDIM;
    float* Ob = out + (size_t)b * CDIM * NDIM;
    const int colw = 16 * w + g;
    #pragma unroll
    for (int h = 0; h < 4; h++) {
        __syncthreads();
        #pragma unroll
        for (int k = 0; k < 8; k++) {
            const int ot = 8 * h + k;
            const int ol = 8 * k + 2 * tg;
            sE[ol * 132 + colw]           = racc[ot][0];
            sE[(ol + 1) * 132 + colw]     = racc[ot][1];
            sE[ol * 132 + colw + 8]       = racc[ot][2];
            sE[(ol + 1) * 132 + colw + 8] = racc[ot][3];
        }
        __syncthreads();
        #pragma unroll
        for (int it = 0; it < 8; it++) {
            const int e = tid + it * 256;
            const int ol = e >> 5, ic = (e & 31) * 4;
            const int o = 64 * h + ol;
            const float4 xv = *(const float4*)(Xb + (size_t)o * NDIM + M0 + ic);
            const float bv = bias[o];
            float4 r;
            r.x = sE[ol * 132 + ic]     + xv.x + bv;
            r.y = sE[ol * 132 + ic + 1] + xv.y + bv;
            r.z = sE[ol * 132 + ic + 2] + xv.z + bv;
            r.w = sE[ol * 132 + ic + 3] + xv.w + bv;
            *(float4*)(Ob + (size_t)o * NDIM + M0 + ic) = r;
        }
    }
}

// ---------------------------------------------------------------------------
extern "C" void kernel_launch(void* const* d_in, const int* in_sizes, int n_in,
                              void* d_out, int out_size) {
    const float* x      = (const float*)d_in[0];
    const float* w_qkv  = (const float*)d_in[1];
    const float* b_qkv  = (const float*)d_in[2];
    const float* w_proj = (const float*)d_in[3];
    const float* b_proj = (const float*)d_in[4];
    float* out = (float*)d_out;

    __nv_bfloat16 *xb, *wqb, *qkv;
    cudaGetSymbolAddress((void**)&xb,  g_xb);
    cudaGetSymbolAddress((void**)&wqb, g_wqkvb);
    cudaGetSymbolAddress((void**)&qkv, g_qkv);

    cudaFuncSetAttribute(flash_attn,
                         cudaFuncAttributeMaxDynamicSharedMemorySize, FLASH_SMEM);

    // fused fp32->bf16 conversions (one launch)
    {
        const int n4 = (BATCH * CDIM * NDIM + OC3 * CDIM + CDIM * CDIM) / 4;
        f2b_all<<<(n4 + 255) / 256, 256>>>(x, w_qkv, w_proj);
    }

    // 1) QKV: C[o][n] = W[o][c] X[c][n] + b
    gemm_bf16<false, true, 2, true><<<dim3(NDIM / 128, OC3 / 128, BATCH), 256>>>(
        wqb, CDIM, 0,
        xb, NDIM, (long)CDIM * NDIM,
        qkv, (long)OC3 * NDIM,
        CDIM, 1.f, b_qkv, nullptr, 0);

    // 2) fused attention + projection + residual -> out
    flash_attn<<<dim3(NDIM / 128, BATCH), 256, FLASH_SMEM>>>(x, b_proj, out);
}